// round 11
// baseline (speedup 1.0000x reference)
#include <cuda_runtime.h>

#define IN_CH 16
#define OUT_CH 64
#define HDIM 32
#define WDIM 32
#define NB 8
#define KHW 9
#define F (IN_CH * KHW)      // 144
#define OCG 8                // out channels per block
#define ROWS 2               // output rows per block
#define CSPLIT 4             // input-channel split within block
#define CPT (IN_CH / CSPLIT) // 4 channels per thread
#define TPB 256              // 32 cols * 2 rows * 4 csplit
#define TW 34                // tile width with halo
#define NTAPS (CPT * KHW)    // 36 taps per thread -> 18 FMNMX3 pairs

__global__ __launch_bounds__(TPB, 7) void normdist_kernel(
    const float* __restrict__ x,      // (8,16,32,32)
    const float* __restrict__ weight, // (64,144)
    const float* __restrict__ bias,   // (64)
    float* __restrict__ out)          // (8,64,32,32)
{
    const int og   = blockIdx.x;           // 0..7 out-channel group (8 ch)
    const int rg   = blockIdx.y;           // 0..15 row group (2 rows)
    const int n    = blockIdx.z;           // 0..7 batch
    const int tid  = threadIdx.x;
    const int cpos = tid & 31;             // 0..31 col
    const int r    = (tid >> 5) & 1;       // 0..1 row
    const int cs   = tid >> 6;             // 0..3 channel quarter (warp-uniform)

    const int row0 = rg * ROWS;

    __shared__ float xs[IN_CH][ROWS + 2][TW];             // 8704 B
    __shared__ __align__(16) float wT[F][OCG];            // 4608 B
    __shared__ float ps[CSPLIT - 1][ROWS][32][OCG + 1];   // 6912 B
                                                          // total 20224 B

    // ---- transposed weights: wT[f][oo] = weight[(og*8+oo)*144 + f]
    {
        const float* wsrc = weight + og * OCG * F;
        #pragma unroll
        for (int k = 0; k < 5; k++) {
            int idx = tid + k * TPB;
            if (idx < F * OCG) {
                int oo = idx & (OCG - 1);
                int f  = idx >> 3;
                wT[f][oo] = wsrc[oo * F + f];
            }
        }
    }

    // ---- x tile with halo; shift-only indexing (64 (c,rr) pairs x 4 lanes)
    {
        const float* xn = x + (size_t)n * IN_CH * HDIM * WDIM;
        const int pair = tid >> 2;             // 0..63
        const int l4   = tid & 3;
        const int c    = pair >> 2;            // 0..15
        const int rr   = pair & 3;             // 0..3
        const int gr   = row0 - 1 + rr;
        const bool rok = (gr >= 0) && (gr < HDIM);
        const float* src = xn + (c * HDIM + gr) * WDIM;
        float* dst = &xs[c][rr][0];
        #pragma unroll
        for (int e = 0; e < 9; e++) {
            int cc = l4 + e * 4;
            if (cc < TW) {
                int gc = cc - 1;
                float v = 0.0f;
                if (rok && gc >= 0 && gc < WDIM) v = src[gc];
                dst[cc] = v;
            }
        }
    }
    __syncthreads();

    float acc[OCG];
    #pragma unroll
    for (int o = 0; o < OCG; o++) acc[o] = 0.0f;   // |.| >= 0

    const float* xbase = &xs[cs * CPT][r][cpos];
    const float* wbase = &wT[cs * CPT * KHW][0];

    // ---- 36 taps processed as 18 exact FMNMX3 pairs (pairs may cross channels)
    #pragma unroll
    for (int pr = 0; pr < NTAPS / 2; pr++) {
        const int tA = 2 * pr, tB = 2 * pr + 1;
        // tap -> (channel, kernel row, kernel col), all compile-time
        const int cA = tA / KHW, kA = tA % KHW, iA = kA / 3, jA = kA % 3;
        const int cB = tB / KHW, kB = tB % KHW, iB = kB / 3, jB = kB % 3;

        const float pA = xbase[cA * (ROWS + 2) * TW + iA * TW + jA];
        const float pB = xbase[cB * (ROWS + 2) * TW + iB * TW + jB];

        const float4* wA = reinterpret_cast<const float4*>(wbase + tA * OCG);
        const float4* wB = reinterpret_cast<const float4*>(wbase + tB * OCG);
        float4 a0 = wA[0], a1 = wA[1];
        float4 b0 = wB[0], b1 = wB[1];

        acc[0] = fmaxf(fmaxf(acc[0], fabsf(pA - a0.x)), fabsf(pB - b0.x));
        acc[1] = fmaxf(fmaxf(acc[1], fabsf(pA - a0.y)), fabsf(pB - b0.y));
        acc[2] = fmaxf(fmaxf(acc[2], fabsf(pA - a0.z)), fabsf(pB - b0.z));
        acc[3] = fmaxf(fmaxf(acc[3], fabsf(pA - a0.w)), fabsf(pB - b0.w));
        acc[4] = fmaxf(fmaxf(acc[4], fabsf(pA - a1.x)), fabsf(pB - b1.x));
        acc[5] = fmaxf(fmaxf(acc[5], fabsf(pA - a1.y)), fabsf(pB - b1.y));
        acc[6] = fmaxf(fmaxf(acc[6], fabsf(pA - a1.z)), fabsf(pB - b1.z));
        acc[7] = fmaxf(fmaxf(acc[7], fabsf(pA - a1.w)), fabsf(pB - b1.w));
    }

    // ---- reduce the 4 channel-quarters
    if (cs > 0) {
        float* p = &ps[cs - 1][r][cpos][0];
        #pragma unroll
        for (int o = 0; o < OCG; o++) p[o] = acc[o];
    }
    __syncthreads();

    if (cs == 0) {
        const int orow = row0 + r;
        float* outp = out + (((size_t)n * OUT_CH + og * OCG) * HDIM + orow) * WDIM + cpos;
        #pragma unroll
        for (int o = 0; o < OCG; o++) {
            float v = fmaxf(fmaxf(acc[o], ps[0][r][cpos][o]),
                            fmaxf(ps[1][r][cpos][o], ps[2][r][cpos][o]));
            outp[(size_t)o * HDIM * WDIM] = v + __ldg(&bias[og * OCG + o]);
        }
    }
}

extern "C" void kernel_launch(void* const* d_in, const int* in_sizes, int n_in,
                              void* d_out, int out_size) {
    const float* x      = (const float*)d_in[0];
    const float* weight = (const float*)d_in[1];
    const float* bias   = (const float*)d_in[2];
    float* out          = (float*)d_out;

    dim3 grid(OUT_CH / OCG, HDIM / ROWS, NB);   // (8, 16, 8) = 1024 blocks
    normdist_kernel<<<grid, TPB>>>(x, weight, bias, out);
}

// round 12
// speedup vs baseline: 1.0132x; 1.0132x over previous
#include <cuda_runtime.h>

#define IN_CH 16
#define OUT_CH 64
#define HDIM 32
#define WDIM 32
#define NB 8
#define KHW 9
#define F (IN_CH * KHW)      // 144
#define OCG 8                // out channels per block
#define ROWS 2               // output rows per block
#define NCP 16               // column pairs (2 cols/thread)
#define CSPLIT 4             // input-channel split
#define CPT (IN_CH / CSPLIT) // 4 channels per thread
#define TPB 128              // 16 cp * 2 rows * 4 cs
#define TW 34                // tile width with halo
#define PSP 18               // ps inner stride

__global__ __launch_bounds__(TPB, 8) void normdist_kernel(
    const float* __restrict__ x,      // (8,16,32,32)
    const float* __restrict__ weight, // (64,144)
    const float* __restrict__ bias,   // (64)
    float* __restrict__ out)          // (8,64,32,32)
{
    const int og  = blockIdx.x;            // 0..7 out-channel group
    const int rg  = blockIdx.y;            // 0..15 row group
    const int n   = blockIdx.z;            // 0..7 batch
    const int tid = threadIdx.x;
    const int cp  = tid & 15;              // 0..15 column pair
    const int r   = (tid >> 4) & 1;        // 0..1 row
    const int cs  = tid >> 5;              // 0..3 channel quarter (warp-uniform)

    const int row0 = rg * ROWS;

    __shared__ float xs[IN_CH][ROWS + 2][TW];               // 8704 B
    __shared__ __align__(16) float wT[F][OCG];              // 4608 B
    __shared__ float ps[CSPLIT - 1][ROWS][NCP][PSP];        // 6912 B
                                                            // total 20224 B

    // ---- transposed weights: wT[f][oo] = weight[(og*8+oo)*144 + f]
    {
        const float* wsrc = weight + og * OCG * F;
        #pragma unroll
        for (int k = 0; k < 9; k++) {          // ceil(1152/128)
            int idx = tid + k * TPB;
            if (idx < F * OCG) {
                int oo = idx & (OCG - 1);
                int f  = idx >> 3;
                wT[f][oo] = wsrc[oo * F + f];
            }
        }
    }

    // ---- x tile with halo; shift-only indexing (64 (c,rr) pairs x 2 lanes)
    {
        const float* xn = x + (size_t)n * IN_CH * HDIM * WDIM;
        const int pair = tid >> 1;             // 0..63
        const int l2   = tid & 1;
        const int c    = pair >> 2;            // 0..15
        const int rr   = pair & 3;             // 0..3
        const int gr   = row0 - 1 + rr;
        const bool rok = (gr >= 0) && (gr < HDIM);
        const float* src = xn + (c * HDIM + gr) * WDIM;
        float* dst = &xs[c][rr][0];
        #pragma unroll
        for (int e = 0; e < 17; e++) {         // 17*2=34
            int cc = l2 + e * 2;
            int gc = cc - 1;
            float v = 0.0f;
            if (rok && gc >= 0 && gc < WDIM) v = src[gc];
            dst[cc] = v;
        }
    }
    __syncthreads();

    float accA[OCG], accB[OCG];
    #pragma unroll
    for (int o = 0; o < OCG; o++) { accA[o] = 0.0f; accB[o] = 0.0f; }

    const float* xbase = &xs[cs * CPT][r][2 * cp];
    const float* wbase = &wT[cs * CPT * KHW][0];

    #pragma unroll
    for (int ci = 0; ci < CPT; ci++) {
        // 3 rows x 4 cols patch segment via aligned LDS.64
        float v[3][4];
        #pragma unroll
        for (int i = 0; i < 3; i++) {
            const float2* row = reinterpret_cast<const float2*>(
                xbase + ci * (ROWS + 2) * TW + i * TW);
            float2 a = row[0];
            float2 b = row[1];
            v[i][0] = a.x; v[i][1] = a.y; v[i][2] = b.x; v[i][3] = b.y;
        }

        // taps in PAIRS -> FMNMX3: acc = max(max(acc,|d0|),|d1|)
        #pragma unroll
        for (int tp = 0; tp < 4; tp++) {
            const int t0 = 2 * tp, t1 = 2 * tp + 1;
            const int i0 = t0 / 3, j0 = t0 % 3;
            const int i1 = t1 / 3, j1 = t1 % 3;
            const float4* w0 = reinterpret_cast<const float4*>(
                wbase + (ci * KHW + t0) * OCG);
            const float4* w1 = reinterpret_cast<const float4*>(
                wbase + (ci * KHW + t1) * OCG);
            float4 a0 = w0[0], a1 = w0[1];
            float4 b0 = w1[0], b1 = w1[1];
            const float pA0 = v[i0][j0], pB0 = v[i0][j0 + 1];
            const float pA1 = v[i1][j1], pB1 = v[i1][j1 + 1];
            accA[0] = fmaxf(fmaxf(accA[0], fabsf(pA0 - a0.x)), fabsf(pA1 - b0.x));
            accA[1] = fmaxf(fmaxf(accA[1], fabsf(pA0 - a0.y)), fabsf(pA1 - b0.y));
            accA[2] = fmaxf(fmaxf(accA[2], fabsf(pA0 - a0.z)), fabsf(pA1 - b0.z));
            accA[3] = fmaxf(fmaxf(accA[3], fabsf(pA0 - a0.w)), fabsf(pA1 - b0.w));
            accA[4] = fmaxf(fmaxf(accA[4], fabsf(pA0 - a1.x)), fabsf(pA1 - b1.x));
            accA[5] = fmaxf(fmaxf(accA[5], fabsf(pA0 - a1.y)), fabsf(pA1 - b1.y));
            accA[6] = fmaxf(fmaxf(accA[6], fabsf(pA0 - a1.z)), fabsf(pA1 - b1.z));
            accA[7] = fmaxf(fmaxf(accA[7], fabsf(pA0 - a1.w)), fabsf(pA1 - b1.w));
            accB[0] = fmaxf(fmaxf(accB[0], fabsf(pB0 - a0.x)), fabsf(pB1 - b0.x));
            accB[1] = fmaxf(fmaxf(accB[1], fabsf(pB0 - a0.y)), fabsf(pB1 - b0.y));
            accB[2] = fmaxf(fmaxf(accB[2], fabsf(pB0 - a0.z)), fabsf(pB1 - b0.z));
            accB[3] = fmaxf(fmaxf(accB[3], fabsf(pB0 - a0.w)), fabsf(pB1 - b0.w));
            accB[4] = fmaxf(fmaxf(accB[4], fabsf(pB0 - a1.x)), fabsf(pB1 - b1.x));
            accB[5] = fmaxf(fmaxf(accB[5], fabsf(pB0 - a1.y)), fabsf(pB1 - b1.y));
            accB[6] = fmaxf(fmaxf(accB[6], fabsf(pB0 - a1.z)), fabsf(pB1 - b1.z));
            accB[7] = fmaxf(fmaxf(accB[7], fabsf(pB0 - a1.w)), fabsf(pB1 - b1.w));
        }
        // leftover tap 8 (i=2, j=2)
        {
            const float4* w4 = reinterpret_cast<const float4*>(
                wbase + (ci * KHW + 8) * OCG);
            float4 wa = w4[0], wb = w4[1];
            const float pA = v[2][2], pB = v[2][3];
            accA[0] = fmaxf(accA[0], fabsf(pA - wa.x));
            accA[1] = fmaxf(accA[1], fabsf(pA - wa.y));
            accA[2] = fmaxf(accA[2], fabsf(pA - wa.z));
            accA[3] = fmaxf(accA[3], fabsf(pA - wa.w));
            accA[4] = fmaxf(accA[4], fabsf(pA - wb.x));
            accA[5] = fmaxf(accA[5], fabsf(pA - wb.y));
            accA[6] = fmaxf(accA[6], fabsf(pA - wb.z));
            accA[7] = fmaxf(accA[7], fabsf(pA - wb.w));
            accB[0] = fmaxf(accB[0], fabsf(pB - wa.x));
            accB[1] = fmaxf(accB[1], fabsf(pB - wa.y));
            accB[2] = fmaxf(accB[2], fabsf(pB - wa.z));
            accB[3] = fmaxf(accB[3], fabsf(pB - wa.w));
            accB[4] = fmaxf(accB[4], fabsf(pB - wb.x));
            accB[5] = fmaxf(accB[5], fabsf(pB - wb.y));
            accB[6] = fmaxf(accB[6], fabsf(pB - wb.z));
            accB[7] = fmaxf(accB[7], fabsf(pB - wb.w));
        }
    }

    // ---- reduce the 4 channel-quarters
    if (cs > 0) {
        float* p = &ps[cs - 1][r][cp][0];
        #pragma unroll
        for (int o = 0; o < OCG; o++) { p[o] = accA[o]; p[OCG + o] = accB[o]; }
    }
    __syncthreads();

    if (cs == 0) {
        const int orow = row0 + r;
        float* outp = out + (((size_t)n * OUT_CH + og * OCG) * HDIM + orow) * WDIM + 2 * cp;
        #pragma unroll
        for (int o = 0; o < OCG; o++) {
            float a = fmaxf(fmaxf(accA[o], ps[0][r][cp][o]),
                            fmaxf(ps[1][r][cp][o], ps[2][r][cp][o]));
            float b = fmaxf(fmaxf(accB[o], ps[0][r][cp][OCG + o]),
                            fmaxf(ps[1][r][cp][OCG + o], ps[2][r][cp][OCG + o]));
            const float bi = __ldg(&bias[og * OCG + o]);
            float2 res = make_float2(a + bi, b + bi);
            *reinterpret_cast<float2*>(outp + (size_t)o * HDIM * WDIM) = res;
        }
    }
}

extern "C" void kernel_launch(void* const* d_in, const int* in_sizes, int n_in,
                              void* d_out, int out_size) {
    const float* x      = (const float*)d_in[0];
    const float* weight = (const float*)d_in[1];
    const float* bias   = (const float*)d_in[2];
    float* out          = (float*)d_out;

    dim3 grid(OUT_CH / OCG, HDIM / ROWS, NB);   // (8, 16, 8) = 1024 blocks
    normdist_kernel<<<grid, TPB>>>(x, weight, bias, out);
}